// round 12
// baseline (speedup 1.0000x reference)
#include <cuda_runtime.h>
#include <cuda_fp16.h>
#include <cstdint>

#define NB   32
#define CIN  256
#define COUT 256
#define HH   56
#define WW   56
#define PW   58
#define IMGP 3368             // padded image stride (p dimension)
#define GTAIL (81*256)        // tail guard halves (tap/tile overreach on last image)

#define TM   128
#define TN   96
#define TK   32
#define NSTG 4
#define STG_BYTES 14336       // A 8KB + B 6KB
#define B_OFF 8192
#define SMEM_TOTAL (NSTG*STG_BYTES)   // 56 KB -> 3 CTAs/SM = 172 KB
#define NTHR 192

// channels-last padded input: g_xcl[b][p][ci], fp16
__device__ __align__(256) __half g_xcl[(size_t)NB*IMGP*CIN + GTAIL];
__device__ __align__(256) __half g_wh[COUT*2304];   // weights, k = tap*256 + ci

// ---------------------------------------------------------------------------
// Prep 0: zero ONLY padding borders + tails (interior written by tpad).
// ---------------------------------------------------------------------------
#define BPOS 232
#define BU4_PER_IMG (BPOS*32)                 // 7424 uint4 per image
#define BU4_TOTAL   (NB*BU4_PER_IMG + GTAIL/8)
__global__ void border_kernel() {
    int i = blockIdx.x*blockDim.x + threadIdx.x;
    if (i >= BU4_TOTAL) return;
    size_t off16;
    if (i < NB*BU4_PER_IMG) {
        int b   = i / BU4_PER_IMG;
        int idx = i % BU4_PER_IMG;
        int j   = idx >> 5;
        int c   = idx & 31;
        int p;
        if      (j < 58)  p = j;                       // y = 0 row
        else if (j < 116) p = 57*PW + (j - 58);        // y = 57 row
        else if (j < 172) p = (j - 116 + 1)*PW;        // x = 0 col
        else if (j < 228) p = (j - 172 + 1)*PW + 57;   // x = 57 col
        else              p = 3364 + (j - 228);        // p tail
        off16 = ((size_t)b*IMGP + p)*CIN + c*8;
    } else {
        off16 = (size_t)NB*IMGP*CIN + (size_t)(i - NB*BU4_PER_IMG)*8;
    }
    *(uint4*)(g_xcl + off16) = make_uint4(0,0,0,0);
}

// ---------------------------------------------------------------------------
// Prep 1: transpose-pad  x[b][ci][h][w] (fp32) -> g_xcl[b][(y+1)*58+(x+1)][ci]
// ---------------------------------------------------------------------------
__global__ void tpad_kernel(const float* __restrict__ x) {
    __shared__ __half st[32][68];
    const int tid = threadIdx.x;
    const int pc  = blockIdx.x * 64;
    const int cic = blockIdx.y * 32;
    const int b   = blockIdx.z;
    {
        int ci_r = tid >> 3;
        int pj   = tid & 7;
        const float* src = x + ((size_t)(b*CIN + cic + ci_r)*3136 + pc + pj*8);
        float4 v0 = *(const float4*)(src);
        float4 v1 = *(const float4*)(src + 4);
        st[ci_r][pj*8+0] = __float2half(v0.x);
        st[ci_r][pj*8+1] = __float2half(v0.y);
        st[ci_r][pj*8+2] = __float2half(v0.z);
        st[ci_r][pj*8+3] = __float2half(v0.w);
        st[ci_r][pj*8+4] = __float2half(v1.x);
        st[ci_r][pj*8+5] = __float2half(v1.y);
        st[ci_r][pj*8+6] = __float2half(v1.z);
        st[ci_r][pj*8+7] = __float2half(v1.w);
    }
    __syncthreads();
    {
        int pw = tid >> 2;
        int g  = tid & 3;
        int p  = pc + pw;
        int y  = p / 56, xx = p % 56;
        int ppad = (y+1)*PW + (xx+1);
        __half h[8];
        #pragma unroll
        for (int j = 0; j < 8; ++j) h[j] = st[g*8+j][pw];
        __half* dst = g_xcl + ((size_t)b*IMGP + ppad)*CIN + cic + g*8;
        *(uint4*)dst = *(uint4*)h;
    }
}

// ---------------------------------------------------------------------------
// Prep 2: weights -> fp16, k = tap*256 + ci
// ---------------------------------------------------------------------------
__global__ void wprep_kernel(const float* __restrict__ qw) {
    int i = blockIdx.x*blockDim.x + threadIdx.x;
    if (i < COUT*2304) {
        int co = i / 2304, rest = i % 2304;
        int ci = rest / 9, tap = rest % 9;
        g_wh[co*2304 + tap*256 + ci] = __float2half(qw[i]);
    }
}

// ---------------------------------------------------------------------------
// PTX helpers
// ---------------------------------------------------------------------------
__device__ __forceinline__ uint32_t smem_u32(const void* p) {
    uint32_t a;
    asm("{ .reg .u64 t; cvta.to.shared.u64 t, %1; cvt.u32.u64 %0, t; }"
        : "=r"(a) : "l"(p));
    return a;
}
__device__ __forceinline__ void cp_async16(uint32_t dst, const void* src) {
    asm volatile("cp.async.cg.shared.global [%0], [%1], 16;\n" :: "r"(dst), "l"(src));
}
__device__ __forceinline__ void cp_commit() {
    asm volatile("cp.async.commit_group;\n" ::: "memory");
}
template <int N>
__device__ __forceinline__ void cp_wait() {
    asm volatile("cp.async.wait_group %0;\n" :: "n"(N) : "memory");
}
__device__ __forceinline__ void ldsm4(uint32_t* r, uint32_t a) {
    asm volatile("ldmatrix.sync.aligned.m8n8.x4.shared.b16 {%0,%1,%2,%3}, [%4];"
        : "=r"(r[0]), "=r"(r[1]), "=r"(r[2]), "=r"(r[3]) : "r"(a));
}
__device__ __forceinline__ void mma16816(float* c, const uint32_t* a, const uint32_t* b) {
    asm("mma.sync.aligned.m16n8k16.row.col.f32.f16.f16.f32 "
        "{%0,%1,%2,%3}, {%4,%5,%6,%7}, {%8,%9}, {%0,%1,%2,%3};"
        : "+f"(c[0]), "+f"(c[1]), "+f"(c[2]), "+f"(c[3])
        : "r"(a[0]), "r"(a[1]), "r"(a[2]), "r"(a[3]), "r"(b[0]), "r"(b[1]));
}

// ---------------------------------------------------------------------------
// Implicit-GEMM conv:  D[co,p'] = sum_k W[co,k] * X[k,p']
// K = 2304 as 72 chunks of 32, windows of 2 chunks, 4-stage smem ring.
// 192 threads = 6 warps (wm2 x wn3), warp tile 64co x 32n (64 acc regs).
// grid = (34 p'-tiles of 96, 2 co-tiles, 32 b), 3 CTAs/SM -> 18 warps/SM.
// ---------------------------------------------------------------------------
__global__ __launch_bounds__(NTHR, 3)
void conv_kernel(const float* __restrict__ scale,
                 const float* __restrict__ bias,
                 float* __restrict__ out)
{
    extern __shared__ __align__(16) char smem[];
    const uint32_t sb = smem_u32(smem);

    const int tid  = threadIdx.x;
    const int lane = tid & 31;
    const int warp = tid >> 5;
    const int wm   = warp & 1;          // 2 m-warps (co, 64 each)
    const int wn   = warp >> 1;         // 3 n-warps (p', 32 each)
    const int b       = blockIdx.z;
    const int co_base = blockIdx.y * TM;
    const int p0      = blockIdx.x * TN;

    float acc[4][4][4];                 // [mt 16co][nt 8n][regs]
    #pragma unroll
    for (int mt = 0; mt < 4; ++mt)
        #pragma unroll
        for (int nt = 0; nt < 4; ++nt)
            #pragma unroll
            for (int r = 0; r < 4; ++r) acc[mt][nt][r] = 0.f;

    // Load K-chunk kc into slot kc%4. A: 128 rows x 64B (512 x 16B chunks),
    // B: 96 rows x 64B (384 chunks). 896 chunks over 192 threads (<=5 each).
    // Swizzle chunk' = c ^ ((row>>1)&3).
    auto loadStage = [&](int kc) {
        int st  = kc % NSTG;
        int tap = kc >> 3, ci0 = (kc & 7) * TK;
        int tap_off = (tap/3)*PW + (tap%3);
        uint32_t base = sb + (uint32_t)st*STG_BYTES;
        #pragma unroll
        for (int t = 0; t < 5; ++t) {
            int idx = tid + t*NTHR;
            if (t < 4 || idx < 896) {
                if (idx < 512) {
                    int row = idx >> 2, c = idx & 3;
                    const __half* src = g_wh + (size_t)(co_base + row)*2304
                                             + tap*256 + ci0 + c*8;
                    uint32_t sw = (uint32_t)((c ^ ((row>>1)&3)) << 4);
                    cp_async16(base + (uint32_t)row*64 + sw, src);
                } else {
                    int j = idx - 512;
                    int row = j >> 2, c = j & 3;
                    const __half* src = g_xcl + ((size_t)b*IMGP + p0 + row + tap_off)*CIN
                                              + ci0 + c*8;
                    uint32_t sw = (uint32_t)((c ^ ((row>>1)&3)) << 4);
                    cp_async16(base + B_OFF + (uint32_t)row*64 + sw, src);
                }
            }
        }
        cp_commit();
    };

    auto compute = [&](int kc) {
        int bufi = kc % NSTG;
        uint32_t ab = sb + (uint32_t)bufi*STG_BYTES;
        uint32_t bb = ab + B_OFF;
        #pragma unroll
        for (int s = 0; s < 2; ++s) {       // 2 x K16 steps
            uint32_t a[4][4];
            #pragma unroll
            for (int mt = 0; mt < 4; ++mt) {
                int m  = wm*64 + mt*16 + (lane & 15);
                int kg = s*2 + (lane >> 4);
                ldsm4(a[mt], ab + (uint32_t)m*64 + (uint32_t)((kg ^ ((m>>1)&3)) << 4));
            }
            #pragma unroll
            for (int pr = 0; pr < 2; ++pr) {
                int grp = lane >> 3, r = lane & 7;
                int n = wn*32 + pr*16 + ((grp & 2) << 2) + r;
                int c = s*2 + (grp & 1);
                uint32_t bfr[4];            // (n0,k0)(n0,k8)(n0+8,k0)(n0+8,k8)
                ldsm4(bfr, bb + (uint32_t)n*64 + (uint32_t)((c ^ ((n>>1)&3)) << 4));
                #pragma unroll
                for (int mt = 0; mt < 4; ++mt) {
                    mma16816(acc[mt][2*pr+0], a[mt], &bfr[0]);
                    mma16816(acc[mt][2*pr+1], a[mt], &bfr[2]);
                }
            }
        }
    };

    // ---- 36 windows of 2 chunks (72 chunks total) ---------------------------
    loadStage(0); loadStage(1);

    for (int w = 0; w < 36; ++w) {
        cp_wait<0>();
        __syncthreads();
        int kc = w*2;
        if (w < 35) {
            loadStage(kc+2); loadStage(kc+3);
        }
        compute(kc); compute(kc+1);
    }

    // ---- epilogue: scale*acc + bias, discard x>=56 / y>=56 / p'>=3248 -------
    #pragma unroll
    for (int mt = 0; mt < 4; ++mt) {
        #pragma unroll
        for (int half = 0; half < 2; ++half) {
            int co = co_base + wm*64 + mt*16 + (lane>>2) + half*8;
            float sc = __ldg(&scale[co]);
            float bs = __ldg(&bias[co]);
            #pragma unroll
            for (int nt = 0; nt < 4; ++nt) {
                int n = p0 + wn*32 + nt*8 + (lane&3)*2;
                int y = n / PW, x2 = n % PW;
                if (x2 < WW && y < HH) {
                    float2 v;
                    v.x = sc*acc[mt][nt][half*2+0] + bs;
                    v.y = sc*acc[mt][nt][half*2+1] + bs;
                    *(float2*)&out[(((size_t)b*COUT + co)*HH + y)*WW + x2] = v;
                }
            }
        }
    }
}

// ---------------------------------------------------------------------------
extern "C" void kernel_launch(void* const* d_in, const int* in_sizes, int n_in,
                              void* d_out, int out_size) {
    const float* x     = (const float*)d_in[0];
    const float* scale = (const float*)d_in[1];
    const float* qw    = (const float*)d_in[2];
    const float* bias  = (const float*)d_in[3];
    float* out = (float*)d_out;

    border_kernel<<<(BU4_TOTAL + 255)/256, 256>>>();
    dim3 tg(49, 8, NB);
    tpad_kernel<<<tg, 256>>>(x);
    wprep_kernel<<<(COUT*2304 + 255)/256, 256>>>(qw);

    cudaFuncSetAttribute(conv_kernel,
                         cudaFuncAttributeMaxDynamicSharedMemorySize, SMEM_TOTAL);
    dim3 grid(34, 2, NB);   // 34 p'-tiles of 96 (58*56=3248), 2 co-tiles, 32 b
    conv_kernel<<<grid, NTHR, SMEM_TOTAL>>>(scale, bias, out);
}

// round 13
// speedup vs baseline: 1.0567x; 1.0567x over previous
#include <cuda_runtime.h>
#include <cuda_fp16.h>
#include <cstdint>

#define NB   32
#define CIN  256
#define COUT 256
#define HH   56
#define WW   56
#define PW   58
#define IMGP 3368             // padded image stride (p dimension)
#define GTAIL (81*256)        // tail guard halves (tap/tile overreach on last image)

#define TM   128
#define TN   96
#define TK   32
#define NSTG 4
#define STG_BYTES 14336       // A 8KB + B 6KB
#define B_OFF 8192
#define SMEM_TOTAL (NSTG*STG_BYTES)   // 56 KB -> 3 CTAs/SM
#define NTHR 256

// channels-last padded input: g_xcl[b][p][ci], fp16
__device__ __align__(256) __half g_xcl[(size_t)NB*IMGP*CIN + GTAIL];
__device__ __align__(256) __half g_wh[COUT*2304];   // weights, k = tap*256 + ci

// ---------------------------------------------------------------------------
// Prep 0: zero ONLY padding borders + tails (interior written by tpad).
// ---------------------------------------------------------------------------
#define BPOS 232
#define BU4_PER_IMG (BPOS*32)                 // 7424 uint4 per image
#define BU4_TOTAL   (NB*BU4_PER_IMG + GTAIL/8)
__global__ void border_kernel() {
    int i = blockIdx.x*blockDim.x + threadIdx.x;
    if (i >= BU4_TOTAL) return;
    size_t off16;
    if (i < NB*BU4_PER_IMG) {
        int b   = i / BU4_PER_IMG;
        int idx = i % BU4_PER_IMG;
        int j   = idx >> 5;
        int c   = idx & 31;
        int p;
        if      (j < 58)  p = j;                       // y = 0 row
        else if (j < 116) p = 57*PW + (j - 58);        // y = 57 row
        else if (j < 172) p = (j - 116 + 1)*PW;        // x = 0 col
        else if (j < 228) p = (j - 172 + 1)*PW + 57;   // x = 57 col
        else              p = 3364 + (j - 228);        // p tail
        off16 = ((size_t)b*IMGP + p)*CIN + c*8;
    } else {
        off16 = (size_t)NB*IMGP*CIN + (size_t)(i - NB*BU4_PER_IMG)*8;
    }
    *(uint4*)(g_xcl + off16) = make_uint4(0,0,0,0);
}

// ---------------------------------------------------------------------------
// Prep 1: transpose-pad  x[b][ci][h][w] (fp32) -> g_xcl[b][(y+1)*58+(x+1)][ci]
// ---------------------------------------------------------------------------
__global__ void tpad_kernel(const float* __restrict__ x) {
    __shared__ __half st[32][68];
    const int tid = threadIdx.x;
    const int pc  = blockIdx.x * 64;
    const int cic = blockIdx.y * 32;
    const int b   = blockIdx.z;
    {
        int ci_r = tid >> 3;
        int pj   = tid & 7;
        const float* src = x + ((size_t)(b*CIN + cic + ci_r)*3136 + pc + pj*8);
        float4 v0 = *(const float4*)(src);
        float4 v1 = *(const float4*)(src + 4);
        st[ci_r][pj*8+0] = __float2half(v0.x);
        st[ci_r][pj*8+1] = __float2half(v0.y);
        st[ci_r][pj*8+2] = __float2half(v0.z);
        st[ci_r][pj*8+3] = __float2half(v0.w);
        st[ci_r][pj*8+4] = __float2half(v1.x);
        st[ci_r][pj*8+5] = __float2half(v1.y);
        st[ci_r][pj*8+6] = __float2half(v1.z);
        st[ci_r][pj*8+7] = __float2half(v1.w);
    }
    __syncthreads();
    {
        int pw = tid >> 2;
        int g  = tid & 3;
        int p  = pc + pw;
        int y  = p / 56, xx = p % 56;
        int ppad = (y+1)*PW + (xx+1);
        __half h[8];
        #pragma unroll
        for (int j = 0; j < 8; ++j) h[j] = st[g*8+j][pw];
        __half* dst = g_xcl + ((size_t)b*IMGP + ppad)*CIN + cic + g*8;
        *(uint4*)dst = *(uint4*)h;
    }
}

// ---------------------------------------------------------------------------
// Prep 2: weights -> fp16, k = tap*256 + ci
// ---------------------------------------------------------------------------
__global__ void wprep_kernel(const float* __restrict__ qw) {
    int i = blockIdx.x*blockDim.x + threadIdx.x;
    if (i < COUT*2304) {
        int co = i / 2304, rest = i % 2304;
        int ci = rest / 9, tap = rest % 9;
        g_wh[co*2304 + tap*256 + ci] = __float2half(qw[i]);
    }
}

// ---------------------------------------------------------------------------
// PTX helpers
// ---------------------------------------------------------------------------
__device__ __forceinline__ uint32_t smem_u32(const void* p) {
    uint32_t a;
    asm("{ .reg .u64 t; cvta.to.shared.u64 t, %1; cvt.u32.u64 %0, t; }"
        : "=r"(a) : "l"(p));
    return a;
}
__device__ __forceinline__ void cp_async16(uint32_t dst, const void* src) {
    asm volatile("cp.async.cg.shared.global [%0], [%1], 16;\n" :: "r"(dst), "l"(src));
}
__device__ __forceinline__ void cp_commit() {
    asm volatile("cp.async.commit_group;\n" ::: "memory");
}
template <int N>
__device__ __forceinline__ void cp_wait() {
    asm volatile("cp.async.wait_group %0;\n" :: "n"(N) : "memory");
}
__device__ __forceinline__ void ldsm4(uint32_t* r, uint32_t a) {
    asm volatile("ldmatrix.sync.aligned.m8n8.x4.shared.b16 {%0,%1,%2,%3}, [%4];"
        : "=r"(r[0]), "=r"(r[1]), "=r"(r[2]), "=r"(r[3]) : "r"(a));
}
__device__ __forceinline__ void mma16816(float* c, const uint32_t* a, const uint32_t* b) {
    asm("mma.sync.aligned.m16n8k16.row.col.f32.f16.f16.f32 "
        "{%0,%1,%2,%3}, {%4,%5,%6,%7}, {%8,%9}, {%0,%1,%2,%3};"
        : "+f"(c[0]), "+f"(c[1]), "+f"(c[2]), "+f"(c[3])
        : "r"(a[0]), "r"(a[1]), "r"(a[2]), "r"(a[3]), "r"(b[0]), "r"(b[1]));
}

// ---------------------------------------------------------------------------
// Implicit-GEMM conv:  D[co,p'] = sum_k W[co,k] * X[k,p']
// K = 2304 as 72 chunks of 32, windows of 2 chunks, 4-stage smem ring.
// 256 threads = 8 warps (wm4 x wn2), warp tile 32co x 48n (48 acc regs).
// grid = (34 p'-tiles of 96, 2 co-tiles, 32 b), 3 CTAs/SM -> 24 warps/SM.
// ---------------------------------------------------------------------------
__global__ __launch_bounds__(NTHR, 3)
void conv_kernel(const float* __restrict__ scale,
                 const float* __restrict__ bias,
                 float* __restrict__ out)
{
    extern __shared__ __align__(16) char smem[];
    const uint32_t sb = smem_u32(smem);

    const int tid  = threadIdx.x;
    const int lane = tid & 31;
    const int warp = tid >> 5;
    const int wm   = warp & 3;          // 4 m-warps (co, 32 each)
    const int wn   = warp >> 2;         // 2 n-warps (p', 48 each)
    const int b       = blockIdx.z;
    const int co_base = blockIdx.y * TM;
    const int p0      = blockIdx.x * TN;

    float acc[2][6][4];                 // [mt 16co][nt 8n][regs]
    #pragma unroll
    for (int mt = 0; mt < 2; ++mt)
        #pragma unroll
        for (int nt = 0; nt < 6; ++nt)
            #pragma unroll
            for (int r = 0; r < 4; ++r) acc[mt][nt][r] = 0.f;

    // Load K-chunk kc into slot kc%4. A: 128 rows x 64B (512 x 16B chunks),
    // B: 96 rows x 64B (384 chunks). 896 chunks over 256 threads (<=4 each).
    // Swizzle chunk' = c ^ ((row>>1)&3).
    auto loadStage = [&](int kc) {
        int st  = kc % NSTG;
        int tap = kc >> 3, ci0 = (kc & 7) * TK;
        int tap_off = (tap/3)*PW + (tap%3);
        uint32_t base = sb + (uint32_t)st*STG_BYTES;
        #pragma unroll
        for (int t = 0; t < 4; ++t) {
            int idx = tid + t*NTHR;
            if (t < 3 || idx < 896) {
                if (idx < 512) {
                    int row = idx >> 2, c = idx & 3;
                    const __half* src = g_wh + (size_t)(co_base + row)*2304
                                             + tap*256 + ci0 + c*8;
                    uint32_t sw = (uint32_t)((c ^ ((row>>1)&3)) << 4);
                    cp_async16(base + (uint32_t)row*64 + sw, src);
                } else {
                    int j = idx - 512;
                    int row = j >> 2, c = j & 3;
                    const __half* src = g_xcl + ((size_t)b*IMGP + p0 + row + tap_off)*CIN
                                              + ci0 + c*8;
                    uint32_t sw = (uint32_t)((c ^ ((row>>1)&3)) << 4);
                    cp_async16(base + B_OFF + (uint32_t)row*64 + sw, src);
                }
            }
        }
        cp_commit();
    };

    auto compute = [&](int kc) {
        int bufi = kc % NSTG;
        uint32_t ab = sb + (uint32_t)bufi*STG_BYTES;
        uint32_t bb = ab + B_OFF;
        #pragma unroll
        for (int s = 0; s < 2; ++s) {       // 2 x K16 steps
            uint32_t a[2][4];
            #pragma unroll
            for (int mt = 0; mt < 2; ++mt) {
                int m  = wm*32 + mt*16 + (lane & 15);
                int kg = s*2 + (lane >> 4);
                ldsm4(a[mt], ab + (uint32_t)m*64 + (uint32_t)((kg ^ ((m>>1)&3)) << 4));
            }
            #pragma unroll
            for (int pr = 0; pr < 3; ++pr) {
                int grp = lane >> 3, r = lane & 7;
                int n = wn*48 + pr*16 + ((grp & 2) << 2) + r;
                int c = s*2 + (grp & 1);
                uint32_t bfr[4];            // (n0,k0)(n0,k8)(n0+8,k0)(n0+8,k8)
                ldsm4(bfr, bb + (uint32_t)n*64 + (uint32_t)((c ^ ((n>>1)&3)) << 4));
                #pragma unroll
                for (int mt = 0; mt < 2; ++mt) {
                    mma16816(acc[mt][2*pr+0], a[mt], &bfr[0]);
                    mma16816(acc[mt][2*pr+1], a[mt], &bfr[2]);
                }
            }
        }
    };

    // ---- 36 windows of 2 chunks (72 chunks total) ---------------------------
    loadStage(0); loadStage(1);

    for (int w = 0; w < 36; ++w) {
        cp_wait<0>();
        __syncthreads();
        int kc = w*2;
        if (w < 35) {
            loadStage(kc+2); loadStage(kc+3);
        }
        compute(kc); compute(kc+1);
    }

    // ---- epilogue: scale*acc + bias, discard x>=56 / y>=56 / p'>=3248 -------
    #pragma unroll
    for (int mt = 0; mt < 2; ++mt) {
        #pragma unroll
        for (int half = 0; half < 2; ++half) {
            int co = co_base + wm*32 + mt*16 + (lane>>2) + half*8;
            float sc = __ldg(&scale[co]);
            float bs = __ldg(&bias[co]);
            #pragma unroll
            for (int nt = 0; nt < 6; ++nt) {
                int n = p0 + wn*48 + nt*8 + (lane&3)*2;
                int y = n / PW, x2 = n % PW;
                if (x2 < WW && y < HH) {
                    float2 v;
                    v.x = sc*acc[mt][nt][half*2+0] + bs;
                    v.y = sc*acc[mt][nt][half*2+1] + bs;
                    *(float2*)&out[(((size_t)b*COUT + co)*HH + y)*WW + x2] = v;
                }
            }
        }
    }
}

// ---------------------------------------------------------------------------
extern "C" void kernel_launch(void* const* d_in, const int* in_sizes, int n_in,
                              void* d_out, int out_size) {
    const float* x     = (const float*)d_in[0];
    const float* scale = (const float*)d_in[1];
    const float* qw    = (const float*)d_in[2];
    const float* bias  = (const float*)d_in[3];
    float* out = (float*)d_out;

    border_kernel<<<(BU4_TOTAL + 255)/256, 256>>>();
    dim3 tg(49, 8, NB);
    tpad_kernel<<<tg, 256>>>(x);
    wprep_kernel<<<(COUT*2304 + 255)/256, 256>>>(qw);

    cudaFuncSetAttribute(conv_kernel,
                         cudaFuncAttributeMaxDynamicSharedMemorySize, SMEM_TOTAL);
    dim3 grid(34, 2, NB);   // 34 p'-tiles of 96 (58*56=3248), 2 co-tiles, 32 b
    conv_kernel<<<grid, NTHR, SMEM_TOTAL>>>(scale, bias, out);
}